// round 1
// baseline (speedup 1.0000x reference)
#include <cuda_runtime.h>

#define GN 50000
#define GE 800000
#define GET (GE + GN)   // 850000 edges incl. self loops

// ---------------- scratch (device globals; no allocs allowed) ----------------
__device__ __align__(16) float g_xl1[GN * 256];     // x @ W_l1
__device__ __align__(16) float g_xr1[GN * 256];     // x @ W_r1
__device__ __align__(16) float g_h[GN * 256];       // layer1 output / layer2 input
__device__ __align__(16) float g_score[GET * 4];    // per-edge per-head score -> exp
__device__ __align__(16) float g_m[GN * 4];         // segment max
__device__ __align__(16) float g_denom[GN * 4];     // segment sum of exp
__device__ __align__(16) float g_score2[GET];
__device__ __align__(16) float g_m2[GN];
__device__ __align__(16) float g_denom2[GN];
__device__ __align__(16) float g_hl2[GN * 10];
__device__ __align__(16) float g_hr2[GN * 10];

// ---------------- helpers ----------------
__device__ __forceinline__ void atomicMaxFloat(float* addr, float val) {
    int old = __float_as_int(*addr);
    while (__int_as_float(old) < val) {
        int assumed = old;
        old = atomicCAS((int*)addr, assumed, __float_as_int(val));
        if (old == assumed) break;
    }
}

__device__ __forceinline__ void red_add_v4(float* addr, float a, float b, float c, float d) {
    asm volatile("red.global.add.v4.f32 [%0], {%1,%2,%3,%4};"
                 :: "l"(addr), "f"(a), "f"(b), "f"(c), "f"(d)
                 : "memory");
}

__device__ __forceinline__ float lrelu(float v) { return v > 0.0f ? v : 0.2f * v; }

// ---------------- init ----------------
__global__ void init_kernel(float* __restrict__ out) {
    int i = blockIdx.x * blockDim.x + threadIdx.x;
    if (i < GN * 256) g_h[i] = 0.0f;
    if (i < GN * 4) { g_m[i] = -1e30f; g_denom[i] = 0.0f; }
    if (i < GN)     { g_m2[i] = -1e30f; g_denom2[i] = 0.0f; }
    if (i < GN * 10) out[i] = 0.0f;
}

// ---------------- GEMM1: [N,256] x [256,512] -> xl1 | xr1 ----------------
// 64x64 tile, BK=16, 256 threads, 4x4 per thread.
__global__ void gemm1_kernel(const float* __restrict__ x,
                             const float* __restrict__ Wl,
                             const float* __restrict__ Wr) {
    __shared__ __align__(16) float As[16][68];   // transposed A tile (padded)
    __shared__ __align__(16) float Bs[16][64];
    int bm = blockIdx.x, bn = blockIdx.y;
    const float* B = (bn < 4) ? (Wl + bn * 64) : (Wr + (bn - 4) * 64);
    float* C = (bn < 4) ? g_xl1 : g_xr1;
    int coloff = (bn & 3) * 64;
    int tid = threadIdx.x;
    int tx = tid & 15, ty = tid >> 4;
    int row0 = bm * 64;
    int aRow = tid >> 2;         // 0..63
    int aK = (tid & 3) * 4;      // 0,4,8,12
    int bK = tid >> 4;           // 0..15
    int bC = (tid & 15) * 4;     // 0..60
    float acc[4][4] = {};
    for (int kk = 0; kk < 256; kk += 16) {
        float4 av = make_float4(0.f, 0.f, 0.f, 0.f);
        int ar = row0 + aRow;
        if (ar < GN)
            av = *reinterpret_cast<const float4*>(x + (size_t)ar * 256 + kk + aK);
        As[aK + 0][aRow] = av.x; As[aK + 1][aRow] = av.y;
        As[aK + 2][aRow] = av.z; As[aK + 3][aRow] = av.w;
        float4 bv = *reinterpret_cast<const float4*>(B + (size_t)(kk + bK) * 256 + bC);
        *reinterpret_cast<float4*>(&Bs[bK][bC]) = bv;
        __syncthreads();
#pragma unroll
        for (int k = 0; k < 16; k++) {
            float4 a4 = *reinterpret_cast<const float4*>(&As[k][ty * 4]);
            float4 b4 = *reinterpret_cast<const float4*>(&Bs[k][tx * 4]);
            float aa[4] = {a4.x, a4.y, a4.z, a4.w};
            float bb[4] = {b4.x, b4.y, b4.z, b4.w};
#pragma unroll
            for (int i = 0; i < 4; i++)
#pragma unroll
                for (int j = 0; j < 4; j++)
                    acc[i][j] += aa[i] * bb[j];
        }
        __syncthreads();
    }
#pragma unroll
    for (int i = 0; i < 4; i++) {
        int r = row0 + ty * 4 + i;
        if (r < GN) {
            float4 v = make_float4(acc[i][0], acc[i][1], acc[i][2], acc[i][3]);
            *reinterpret_cast<float4*>(C + (size_t)r * 256 + coloff + tx * 4) = v;
        }
    }
}

// ---------------- layer1 per-edge score (warp per edge) ----------------
__global__ void score1_kernel(const int* __restrict__ ei, const float* __restrict__ att) {
    int gt = blockIdx.x * blockDim.x + threadIdx.x;
    int e = gt >> 5;
    int lane = gt & 31;
    if (e >= GET) return;
    int src, dst;
    if (e < GE) { src = ei[e]; dst = ei[GE + e]; }
    else        { src = dst = e - GE; }
    const float* xl = g_xl1 + (size_t)src * 256;
    const float* xr = g_xr1 + (size_t)dst * 256;
    float part[4] = {0.f, 0.f, 0.f, 0.f};
#pragma unroll
    for (int i = 0; i < 8; i++) {
        int idx = i * 32 + lane;
        float v = lrelu(xl[idx] + xr[idx]);
        part[i >> 1] += v * att[idx];
    }
#pragma unroll
    for (int off = 16; off > 0; off >>= 1) {
#pragma unroll
        for (int h = 0; h < 4; h++)
            part[h] += __shfl_xor_sync(0xffffffffu, part[h], off);
    }
    if (lane < 4) {
        float s = part[lane];
        g_score[(size_t)e * 4 + lane] = s;
        atomicMaxFloat(&g_m[dst * 4 + lane], s);
    }
}

// ---------------- layer1 exp + segment sum ----------------
__global__ void exp1_kernel(const int* __restrict__ ei) {
    int id = blockIdx.x * blockDim.x + threadIdx.x;
    if (id >= GET * 4) return;
    int e = id >> 2, h = id & 3;
    int dst = (e < GE) ? ei[GE + e] : (e - GE);
    float ex = expf(g_score[id] - g_m[dst * 4 + h]);
    g_score[id] = ex;
    atomicAdd(&g_denom[dst * 4 + h], ex);
}

// ---------------- layer1 message aggregation (warp per edge, v4 RED) ----------------
__global__ void agg1_kernel(const int* __restrict__ ei) {
    int gt = blockIdx.x * blockDim.x + threadIdx.x;
    int e = gt >> 5;
    int lane = gt & 31;
    if (e >= GET) return;
    int src, dst;
    if (e < GE) { src = ei[e]; dst = ei[GE + e]; }
    else        { src = dst = e - GE; }
    float alpha[4];
#pragma unroll
    for (int h = 0; h < 4; h++)
        alpha[h] = g_score[(size_t)e * 4 + h] / g_denom[dst * 4 + h];
    const float4* xl4 = reinterpret_cast<const float4*>(g_xl1 + (size_t)src * 256);
    float* outb = g_h + (size_t)dst * 256;
#pragma unroll
    for (int i = 0; i < 2; i++) {
        int q = i * 32 + lane;      // float4 index within the 256-wide row
        float4 v = xl4[q];
        float a = alpha[q >> 4];    // 16 float4 per head
        red_add_v4(outb + q * 4, v.x * a, v.y * a, v.z * a, v.w * a);
    }
}

// ---------------- layer1 bias + relu ----------------
__global__ void bias_relu1_kernel(const float* __restrict__ b1) {
    int i = blockIdx.x * blockDim.x + threadIdx.x;
    if (i >= GN * 256) return;
    float v = g_h[i] + b1[i & 255];
    g_h[i] = v > 0.0f ? v : 0.0f;
}

// ---------------- GEMM2: [N,256] x [256,10] twice ----------------
__global__ void gemm2_kernel(const float* __restrict__ Wl2, const float* __restrict__ Wr2) {
    __shared__ float sW[256 * 20];
    int tid = threadIdx.y * 32 + threadIdx.x;   // 256 threads
    for (int i = tid; i < 256 * 10; i += 256) {
        int k = i / 10, j = i % 10;
        sW[k * 20 + j] = Wl2[i];
        sW[k * 20 + 10 + j] = Wr2[i];
    }
    __syncthreads();
    int node = blockIdx.x * 8 + threadIdx.y;
    if (node >= GN) return;
    int j = threadIdx.x;
    if (j >= 20) return;
    const float* hrow = g_h + (size_t)node * 256;
    float acc = 0.0f;
#pragma unroll 8
    for (int k = 0; k < 256; k++)
        acc += hrow[k] * sW[k * 20 + j];
    if (j < 10) g_hl2[node * 10 + j] = acc;
    else        g_hr2[node * 10 + j - 10] = acc;
}

// ---------------- layer2 per-edge score ----------------
__global__ void score2_kernel(const int* __restrict__ ei, const float* __restrict__ att2) {
    int e = blockIdx.x * blockDim.x + threadIdx.x;
    if (e >= GET) return;
    int src, dst;
    if (e < GE) { src = ei[e]; dst = ei[GE + e]; }
    else        { src = dst = e - GE; }
    float s = 0.0f;
#pragma unroll
    for (int c = 0; c < 10; c++) {
        float v = lrelu(g_hl2[src * 10 + c] + g_hr2[dst * 10 + c]);
        s += v * att2[c];
    }
    g_score2[e] = s;
    atomicMaxFloat(&g_m2[dst], s);
}

__global__ void exp2_kernel(const int* __restrict__ ei) {
    int e = blockIdx.x * blockDim.x + threadIdx.x;
    if (e >= GET) return;
    int dst = (e < GE) ? ei[GE + e] : (e - GE);
    float ex = expf(g_score2[e] - g_m2[dst]);
    g_score2[e] = ex;
    atomicAdd(&g_denom2[dst], ex);
}

__global__ void agg2_kernel(const int* __restrict__ ei, float* __restrict__ out) {
    int e = blockIdx.x * blockDim.x + threadIdx.x;
    if (e >= GET) return;
    int src, dst;
    if (e < GE) { src = ei[e]; dst = ei[GE + e]; }
    else        { src = dst = e - GE; }
    float a = g_score2[e] / g_denom2[dst];
#pragma unroll
    for (int c = 0; c < 10; c++)
        atomicAdd(&out[dst * 10 + c], a * g_hl2[src * 10 + c]);
}

__global__ void bias2_kernel(float* __restrict__ out, const float* __restrict__ b2) {
    int i = blockIdx.x * blockDim.x + threadIdx.x;
    if (i >= GN * 10) return;
    out[i] += b2[i % 10];
}

// ---------------- launch ----------------
extern "C" void kernel_launch(void* const* d_in, const int* in_sizes, int n_in,
                              void* d_out, int out_size) {
    const float* x    = (const float*)d_in[0];
    const int*   ei   = (const int*)d_in[1];
    const float* Wl1  = (const float*)d_in[2];
    const float* Wr1  = (const float*)d_in[3];
    const float* att1 = (const float*)d_in[4];
    const float* b1   = (const float*)d_in[5];
    const float* Wl2  = (const float*)d_in[6];
    const float* Wr2  = (const float*)d_in[7];
    const float* att2 = (const float*)d_in[8];
    const float* b2   = (const float*)d_in[9];
    float* out = (float*)d_out;

    init_kernel<<<(GN * 256 + 255) / 256, 256>>>(out);

    dim3 g1((GN + 63) / 64, 8);
    gemm1_kernel<<<g1, 256>>>(x, Wl1, Wr1);

    score1_kernel<<<(GET + 7) / 8, 256>>>(ei, att1);          // warp per edge
    exp1_kernel<<<(GET * 4 + 255) / 256, 256>>>(ei);
    agg1_kernel<<<(GET + 7) / 8, 256>>>(ei);                  // warp per edge
    bias_relu1_kernel<<<(GN * 256 + 255) / 256, 256>>>(b1);

    gemm2_kernel<<<(GN + 7) / 8, dim3(32, 8)>>>(Wl2, Wr2);

    score2_kernel<<<(GET + 255) / 256, 256>>>(ei, att2);
    exp2_kernel<<<(GET + 255) / 256, 256>>>(ei);
    agg2_kernel<<<(GET + 255) / 256, 256>>>(ei, out);
    bias2_kernel<<<(GN * 10 + 255) / 256, 256>>>(out, b2);
}

// round 2
// speedup vs baseline: 1.5744x; 1.5744x over previous
#include <cuda_runtime.h>
#include <math_constants.h>

#define GN 50000
#define GE 800000
#define GET (GE + GN)   // edges incl. self loops

// ---------------- scratch (device globals; no allocs allowed) ----------------
__device__ __align__(16) float g_xl1[GN * 256];     // x @ W_l1
__device__ __align__(16) float g_xr1[GN * 256];     // x @ W_r1
__device__ __align__(16) float g_h[GN * 256];       // layer1 output / layer2 input
__device__ __align__(16) float g_hl2[GN * 10];
__device__ __align__(16) float g_hr2[GN * 10];
__device__ int g_cnt[GN];
__device__ int g_rowptr[GN + 1];
__device__ int g_cursor[GN];
__device__ int g_csr_src[GET];

__device__ __forceinline__ float lrelu(float v) { return v > 0.0f ? v : 0.2f * v; }

// ---------------- init: zero histogram ----------------
__global__ void zero_cnt_kernel() {
    int i = blockIdx.x * blockDim.x + threadIdx.x;
    if (i < GN) g_cnt[i] = 0;
}

// ---------------- CSR build ----------------
__global__ void hist_kernel(const int* __restrict__ ei) {
    int e = blockIdx.x * blockDim.x + threadIdx.x;
    if (e >= GET) return;
    int dst = (e < GE) ? ei[GE + e] : (e - GE);
    atomicAdd(&g_cnt[dst], 1);
}

__global__ void scan_kernel() {
    __shared__ int s[1024];
    __shared__ int carry;
    int tid = threadIdx.x;
    if (tid == 0) carry = 0;
    __syncthreads();
    for (int base = 0; base < GN; base += 1024) {
        int i = base + tid;
        int v = (i < GN) ? g_cnt[i] : 0;
        s[tid] = v;
        __syncthreads();
#pragma unroll
        for (int off = 1; off < 1024; off <<= 1) {
            int t = (tid >= off) ? s[tid - off] : 0;
            __syncthreads();
            s[tid] += t;
            __syncthreads();
        }
        int excl = s[tid] - v;
        if (i < GN) {
            int r = carry + excl;
            g_rowptr[i] = r;
            g_cursor[i] = r;
        }
        __syncthreads();
        if (tid == 0) carry += s[1023];
        __syncthreads();
    }
    if (tid == 0) g_rowptr[GN] = GET;
}

__global__ void scatter_kernel(const int* __restrict__ ei) {
    int e = blockIdx.x * blockDim.x + threadIdx.x;
    if (e >= GET) return;
    int src, dst;
    if (e < GE) { src = ei[e]; dst = ei[GE + e]; }
    else        { src = dst = e - GE; }
    int pos = atomicAdd(&g_cursor[dst], 1);
    g_csr_src[pos] = src;
}

// ---------------- GEMM1: [N,256] x [256,512] -> xl1 | xr1 ----------------
// 128x64 tile, BK=16, 256 threads, 8x4 per thread, double-buffered.
#define BM 128
#define BN 64
#define BK 16
__global__ void gemm1_kernel(const float* __restrict__ x,
                             const float* __restrict__ Wl,
                             const float* __restrict__ Wr) {
    __shared__ __align__(16) float As[2][BK][BM + 4];
    __shared__ __align__(16) float Bs[2][BK][BN];
    int bm = blockIdx.x, bn = blockIdx.y;
    const float* B = (bn < 4) ? (Wl + bn * 64) : (Wr + (bn - 4) * 64);
    float* C = (bn < 4) ? g_xl1 : g_xr1;
    int coloff = (bn & 3) * 64;
    int tid = threadIdx.x;
    int row0 = bm * BM;
    int aRow = tid >> 2;          // 0..63 (second float4 covers +64)
    int aK = (tid & 3) * 4;       // 0,4,8,12
    int bK = tid >> 4;            // 0..15
    int bC = (tid & 15) * 4;      // 0..60
    int ty = tid >> 4, tx = tid & 15;

    float acc[8][4] = {};
    float4 a0, a1, b0;
    const float4 z4 = make_float4(0.f, 0.f, 0.f, 0.f);

    // prologue: tile 0
    {
        int r0 = row0 + aRow, r1 = r0 + 64;
        a0 = (r0 < GN) ? *reinterpret_cast<const float4*>(x + (size_t)r0 * 256 + aK) : z4;
        a1 = (r1 < GN) ? *reinterpret_cast<const float4*>(x + (size_t)r1 * 256 + aK) : z4;
        b0 = *reinterpret_cast<const float4*>(B + (size_t)bK * 256 + bC);
    }
    As[0][aK + 0][aRow] = a0.x; As[0][aK + 1][aRow] = a0.y;
    As[0][aK + 2][aRow] = a0.z; As[0][aK + 3][aRow] = a0.w;
    As[0][aK + 0][aRow + 64] = a1.x; As[0][aK + 1][aRow + 64] = a1.y;
    As[0][aK + 2][aRow + 64] = a1.z; As[0][aK + 3][aRow + 64] = a1.w;
    *reinterpret_cast<float4*>(&Bs[0][bK][bC]) = b0;
    __syncthreads();

    int cur = 0;
    for (int t = 0; t < 16; t++) {
        if (t < 15) {
            int kk = (t + 1) * BK;
            int r0 = row0 + aRow, r1 = r0 + 64;
            a0 = (r0 < GN) ? *reinterpret_cast<const float4*>(x + (size_t)r0 * 256 + kk + aK) : z4;
            a1 = (r1 < GN) ? *reinterpret_cast<const float4*>(x + (size_t)r1 * 256 + kk + aK) : z4;
            b0 = *reinterpret_cast<const float4*>(B + (size_t)(kk + bK) * 256 + bC);
        }
#pragma unroll
        for (int k = 0; k < BK; k++) {
            float4 A0 = *reinterpret_cast<const float4*>(&As[cur][k][ty * 8]);
            float4 A1 = *reinterpret_cast<const float4*>(&As[cur][k][ty * 8 + 4]);
            float4 Bv = *reinterpret_cast<const float4*>(&Bs[cur][k][tx * 4]);
            float aa[8] = {A0.x, A0.y, A0.z, A0.w, A1.x, A1.y, A1.z, A1.w};
            float bb[4] = {Bv.x, Bv.y, Bv.z, Bv.w};
#pragma unroll
            for (int i = 0; i < 8; i++)
#pragma unroll
                for (int j = 0; j < 4; j++)
                    acc[i][j] += aa[i] * bb[j];
        }
        if (t < 15) {
            int nxt = cur ^ 1;
            As[nxt][aK + 0][aRow] = a0.x; As[nxt][aK + 1][aRow] = a0.y;
            As[nxt][aK + 2][aRow] = a0.z; As[nxt][aK + 3][aRow] = a0.w;
            As[nxt][aK + 0][aRow + 64] = a1.x; As[nxt][aK + 1][aRow + 64] = a1.y;
            As[nxt][aK + 2][aRow + 64] = a1.z; As[nxt][aK + 3][aRow + 64] = a1.w;
            *reinterpret_cast<float4*>(&Bs[nxt][bK][bC]) = b0;
            __syncthreads();
            cur = nxt;
        }
    }
#pragma unroll
    for (int i = 0; i < 8; i++) {
        int r = row0 + ty * 8 + i;
        if (r < GN) {
            float4 v = make_float4(acc[i][0], acc[i][1], acc[i][2], acc[i][3]);
            *reinterpret_cast<float4*>(C + (size_t)r * 256 + coloff + tx * 4) = v;
        }
    }
}

// ---------------- layer1 fused: score + online softmax + aggregate + bias + relu ----------------
// One warp per dst node. Lane owns channels [lane*8, lane*8+8), head = lane>>3.
__global__ void layer1_fused_kernel(const float* __restrict__ att1,
                                    const float* __restrict__ b1) {
    int gt = blockIdx.x * blockDim.x + threadIdx.x;
    int node = gt >> 5;
    int lane = threadIdx.x & 31;
    if (node >= GN) return;

    const float4* xr4 = reinterpret_cast<const float4*>(g_xr1) + (size_t)node * 64;
    float4 xr0 = xr4[lane * 2];
    float4 xr1 = xr4[lane * 2 + 1];
    float4 at0 = reinterpret_cast<const float4*>(att1)[lane * 2];
    float4 at1 = reinterpret_cast<const float4*>(att1)[lane * 2 + 1];

    float4 acc0 = make_float4(0.f, 0.f, 0.f, 0.f);
    float4 acc1 = make_float4(0.f, 0.f, 0.f, 0.f);
    float m = -CUDART_INF_F, d = 0.0f;

    int beg = g_rowptr[node], end = g_rowptr[node + 1];
    for (int j = beg; j < end; j++) {
        int src = g_csr_src[j];
        const float4* xl4 = reinterpret_cast<const float4*>(g_xl1) + (size_t)src * 64;
        float4 xl0 = __ldg(&xl4[lane * 2]);
        float4 xl1 = __ldg(&xl4[lane * 2 + 1]);

        float t = lrelu(xl0.x + xr0.x) * at0.x + lrelu(xl0.y + xr0.y) * at0.y
                + lrelu(xl0.z + xr0.z) * at0.z + lrelu(xl0.w + xr0.w) * at0.w
                + lrelu(xl1.x + xr1.x) * at1.x + lrelu(xl1.y + xr1.y) * at1.y
                + lrelu(xl1.z + xr1.z) * at1.z + lrelu(xl1.w + xr1.w) * at1.w;
        // reduce within 8-lane head group
        t += __shfl_xor_sync(0xffffffffu, t, 4);
        t += __shfl_xor_sync(0xffffffffu, t, 2);
        t += __shfl_xor_sync(0xffffffffu, t, 1);

        // online softmax update
        float mn = fmaxf(m, t);
        float f = __expf(m - mn);
        float e = __expf(t - mn);
        d = d * f + e;
        acc0.x = acc0.x * f + e * xl0.x; acc0.y = acc0.y * f + e * xl0.y;
        acc0.z = acc0.z * f + e * xl0.z; acc0.w = acc0.w * f + e * xl0.w;
        acc1.x = acc1.x * f + e * xl1.x; acc1.y = acc1.y * f + e * xl1.y;
        acc1.z = acc1.z * f + e * xl1.z; acc1.w = acc1.w * f + e * xl1.w;
        m = mn;
    }

    float inv = 1.0f / d;
    float4 bb0 = reinterpret_cast<const float4*>(b1)[lane * 2];
    float4 bb1 = reinterpret_cast<const float4*>(b1)[lane * 2 + 1];
    float4 o0, o1;
    o0.x = fmaxf(acc0.x * inv + bb0.x, 0.f); o0.y = fmaxf(acc0.y * inv + bb0.y, 0.f);
    o0.z = fmaxf(acc0.z * inv + bb0.z, 0.f); o0.w = fmaxf(acc0.w * inv + bb0.w, 0.f);
    o1.x = fmaxf(acc1.x * inv + bb1.x, 0.f); o1.y = fmaxf(acc1.y * inv + bb1.y, 0.f);
    o1.z = fmaxf(acc1.z * inv + bb1.z, 0.f); o1.w = fmaxf(acc1.w * inv + bb1.w, 0.f);
    float4* out4 = reinterpret_cast<float4*>(g_h) + (size_t)node * 64;
    out4[lane * 2] = o0;
    out4[lane * 2 + 1] = o1;
}

// ---------------- GEMM2: [N,256] x [256,10] twice ----------------
__global__ void gemm2_kernel(const float* __restrict__ Wl2, const float* __restrict__ Wr2) {
    __shared__ float sW[256 * 20];
    int tid = threadIdx.y * 32 + threadIdx.x;
    for (int i = tid; i < 256 * 10; i += 256) {
        int k = i / 10, j = i % 10;
        sW[k * 20 + j] = Wl2[i];
        sW[k * 20 + 10 + j] = Wr2[i];
    }
    __syncthreads();
    int node = blockIdx.x * 8 + threadIdx.y;
    if (node >= GN) return;
    int j = threadIdx.x;
    if (j >= 20) return;
    const float* hrow = g_h + (size_t)node * 256;
    float acc = 0.0f;
#pragma unroll 8
    for (int k = 0; k < 256; k++)
        acc += hrow[k] * sW[k * 20 + j];
    if (j < 10) g_hl2[node * 10 + j] = acc;
    else        g_hr2[node * 10 + j - 10] = acc;
}

// ---------------- layer2 fused ----------------
__global__ void layer2_fused_kernel(const float* __restrict__ att2,
                                    const float* __restrict__ b2,
                                    float* __restrict__ out) {
    int gt = blockIdx.x * blockDim.x + threadIdx.x;
    int node = gt >> 5;
    int lane = threadIdx.x & 31;
    if (node >= GN) return;

    float hr = (lane < 10) ? g_hr2[node * 10 + lane] : 0.0f;
    float at = (lane < 10) ? att2[lane] : 0.0f;
    float m = -CUDART_INF_F, d = 0.0f, acc = 0.0f;

    int beg = g_rowptr[node], end = g_rowptr[node + 1];
    for (int j = beg; j < end; j++) {
        int src = g_csr_src[j];
        float hl = (lane < 10) ? __ldg(&g_hl2[src * 10 + lane]) : 0.0f;
        float v = lrelu(hl + hr) * at;
        v += __shfl_xor_sync(0xffffffffu, v, 16);
        v += __shfl_xor_sync(0xffffffffu, v, 8);
        v += __shfl_xor_sync(0xffffffffu, v, 4);
        v += __shfl_xor_sync(0xffffffffu, v, 2);
        v += __shfl_xor_sync(0xffffffffu, v, 1);
        float s = v;
        float mn = fmaxf(m, s);
        float f = __expf(m - mn);
        float e = __expf(s - mn);
        d = d * f + e;
        acc = acc * f + e * hl;
        m = mn;
    }
    if (lane < 10)
        out[node * 10 + lane] = acc / d + b2[lane];
}

// ---------------- launch ----------------
extern "C" void kernel_launch(void* const* d_in, const int* in_sizes, int n_in,
                              void* d_out, int out_size) {
    const float* x    = (const float*)d_in[0];
    const int*   ei   = (const int*)d_in[1];
    const float* Wl1  = (const float*)d_in[2];
    const float* Wr1  = (const float*)d_in[3];
    const float* att1 = (const float*)d_in[4];
    const float* b1   = (const float*)d_in[5];
    const float* Wl2  = (const float*)d_in[6];
    const float* Wr2  = (const float*)d_in[7];
    const float* att2 = (const float*)d_in[8];
    const float* b2   = (const float*)d_in[9];
    float* out = (float*)d_out;

    zero_cnt_kernel<<<(GN + 255) / 256, 256>>>();
    hist_kernel<<<(GET + 255) / 256, 256>>>(ei);

    dim3 g1((GN + BM - 1) / BM, 8);
    gemm1_kernel<<<g1, 256>>>(x, Wl1, Wr1);

    scan_kernel<<<1, 1024>>>();
    scatter_kernel<<<(GET + 255) / 256, 256>>>(ei);

    layer1_fused_kernel<<<(GN * 32 + 255) / 256, 256>>>(att1, b1);

    gemm2_kernel<<<(GN + 7) / 8, dim3(32, 8)>>>(Wl2, Wr2);

    layer2_fused_kernel<<<(GN * 32 + 255) / 256, 256>>>(att2, b2, out);
}

// round 3
// speedup vs baseline: 1.8139x; 1.1521x over previous
#include <cuda_runtime.h>
#include <math_constants.h>

#define GN 50000
#define GE 800000
#define GET (GE + GN)   // edges incl. self loops
#define NSCAN_BLK 49    // ceil(GN/1024)

// ---------------- scratch (device globals; no allocs allowed) ----------------
__device__ __align__(16) float g_xl1[GN * 256];     // x @ W_l1
__device__ __align__(16) float g_xr1[GN * 256];     // x @ W_r1
__device__ __align__(16) float g_h[GN * 256];       // layer1 output / layer2 input
__device__ __align__(16) float g_hl2[GN * 10];
__device__ __align__(16) float g_hr2[GN * 10];
__device__ int g_cnt[GN];
__device__ int g_rowptr[GN + 1];
__device__ int g_cursor[GN];
__device__ int g_csr_src[GET];
__device__ int g_bsum[NSCAN_BLK];
__device__ int g_boff[NSCAN_BLK];

__device__ __forceinline__ float lrelu(float v) { return v > 0.0f ? v : 0.2f * v; }

// ---------------- init: zero histogram ----------------
__global__ void zero_cnt_kernel() {
    int i = blockIdx.x * blockDim.x + threadIdx.x;
    if (i < GN) g_cnt[i] = 0;
}

// ---------------- CSR build ----------------
__global__ void hist_kernel(const int* __restrict__ ei) {
    int e = blockIdx.x * blockDim.x + threadIdx.x;
    if (e >= GET) return;
    int dst = (e < GE) ? ei[GE + e] : (e - GE);
    atomicAdd(&g_cnt[dst], 1);
}

// multi-block scan, pass 1: per-block exclusive scan + block totals
__global__ void scan1_kernel() {
    __shared__ int warp_tot[32];
    int tid = threadIdx.x;
    int i = blockIdx.x * 1024 + tid;
    int lane = tid & 31, wid = tid >> 5;
    int v = (i < GN) ? g_cnt[i] : 0;
    // warp inclusive scan
    int s = v;
#pragma unroll
    for (int off = 1; off < 32; off <<= 1) {
        int t = __shfl_up_sync(0xffffffffu, s, off);
        if (lane >= off) s += t;
    }
    if (lane == 31) warp_tot[wid] = s;
    __syncthreads();
    if (wid == 0) {
        int w = warp_tot[lane];
        int ws = w;
#pragma unroll
        for (int off = 1; off < 32; off <<= 1) {
            int t = __shfl_up_sync(0xffffffffu, ws, off);
            if (lane >= off) ws += t;
        }
        warp_tot[lane] = ws - w;   // exclusive warp offsets
        if (lane == 31) g_bsum[blockIdx.x] = ws;  // block total
    }
    __syncthreads();
    int excl = s - v + warp_tot[wid];
    if (i < GN) g_rowptr[i] = excl;   // temp: block-local exclusive
}

// pass 2: scan the block totals (1 block, >=NSCAN_BLK threads in 2 warps)
__global__ void scan2_kernel() {
    int tid = threadIdx.x;   // 64 threads
    __shared__ int sh[64];
    int v = (tid < NSCAN_BLK) ? g_bsum[tid] : 0;
    sh[tid] = v;
    __syncthreads();
    if (tid == 0) {
        int run = 0;
        for (int b = 0; b < NSCAN_BLK; b++) { g_boff[b] = run; run += sh[b]; }
        g_rowptr[GN] = GET;
    }
}

// pass 3: add block offsets
__global__ void scan3_kernel() {
    int i = blockIdx.x * 1024 + threadIdx.x;
    if (i >= GN) return;
    int r = g_rowptr[i] + g_boff[blockIdx.x];
    g_rowptr[i] = r;
    g_cursor[i] = r;
}

__global__ void scatter_kernel(const int* __restrict__ ei) {
    int e = blockIdx.x * blockDim.x + threadIdx.x;
    if (e >= GET) return;
    int src, dst;
    if (e < GE) { src = ei[e]; dst = ei[GE + e]; }
    else        { src = dst = e - GE; }
    int pos = atomicAdd(&g_cursor[dst], 1);
    g_csr_src[pos] = src;
}

// ---------------- GEMM1: [N,256] x [256,512] -> xl1 | xr1 ----------------
// 128x64 tile, BK=16, 256 threads, 8x4 per thread, double-buffered.
#define BM 128
#define BN 64
#define BK 16
__global__ void gemm1_kernel(const float* __restrict__ x,
                             const float* __restrict__ Wl,
                             const float* __restrict__ Wr) {
    __shared__ __align__(16) float As[2][BK][BM + 4];
    __shared__ __align__(16) float Bs[2][BK][BN];
    int bm = blockIdx.x, bn = blockIdx.y;
    const float* B = (bn < 4) ? (Wl + bn * 64) : (Wr + (bn - 4) * 64);
    float* C = (bn < 4) ? g_xl1 : g_xr1;
    int coloff = (bn & 3) * 64;
    int tid = threadIdx.x;
    int row0 = bm * BM;
    int aRow = tid >> 2;
    int aK = (tid & 3) * 4;
    int bK = tid >> 4;
    int bC = (tid & 15) * 4;
    int ty = tid >> 4, tx = tid & 15;

    float acc[8][4] = {};
    float4 a0, a1, b0;
    const float4 z4 = make_float4(0.f, 0.f, 0.f, 0.f);

    {
        int r0 = row0 + aRow, r1 = r0 + 64;
        a0 = (r0 < GN) ? *reinterpret_cast<const float4*>(x + (size_t)r0 * 256 + aK) : z4;
        a1 = (r1 < GN) ? *reinterpret_cast<const float4*>(x + (size_t)r1 * 256 + aK) : z4;
        b0 = *reinterpret_cast<const float4*>(B + (size_t)bK * 256 + bC);
    }
    As[0][aK + 0][aRow] = a0.x; As[0][aK + 1][aRow] = a0.y;
    As[0][aK + 2][aRow] = a0.z; As[0][aK + 3][aRow] = a0.w;
    As[0][aK + 0][aRow + 64] = a1.x; As[0][aK + 1][aRow + 64] = a1.y;
    As[0][aK + 2][aRow + 64] = a1.z; As[0][aK + 3][aRow + 64] = a1.w;
    *reinterpret_cast<float4*>(&Bs[0][bK][bC]) = b0;
    __syncthreads();

    int cur = 0;
    for (int t = 0; t < 16; t++) {
        if (t < 15) {
            int kk = (t + 1) * BK;
            int r0 = row0 + aRow, r1 = r0 + 64;
            a0 = (r0 < GN) ? *reinterpret_cast<const float4*>(x + (size_t)r0 * 256 + kk + aK) : z4;
            a1 = (r1 < GN) ? *reinterpret_cast<const float4*>(x + (size_t)r1 * 256 + kk + aK) : z4;
            b0 = *reinterpret_cast<const float4*>(B + (size_t)(kk + bK) * 256 + bC);
        }
#pragma unroll
        for (int k = 0; k < BK; k++) {
            float4 A0 = *reinterpret_cast<const float4*>(&As[cur][k][ty * 8]);
            float4 A1 = *reinterpret_cast<const float4*>(&As[cur][k][ty * 8 + 4]);
            float4 Bv = *reinterpret_cast<const float4*>(&Bs[cur][k][tx * 4]);
            float aa[8] = {A0.x, A0.y, A0.z, A0.w, A1.x, A1.y, A1.z, A1.w};
            float bb[4] = {Bv.x, Bv.y, Bv.z, Bv.w};
#pragma unroll
            for (int i = 0; i < 8; i++)
#pragma unroll
                for (int j = 0; j < 4; j++)
                    acc[i][j] += aa[i] * bb[j];
        }
        if (t < 15) {
            int nxt = cur ^ 1;
            As[nxt][aK + 0][aRow] = a0.x; As[nxt][aK + 1][aRow] = a0.y;
            As[nxt][aK + 2][aRow] = a0.z; As[nxt][aK + 3][aRow] = a0.w;
            As[nxt][aK + 0][aRow + 64] = a1.x; As[nxt][aK + 1][aRow + 64] = a1.y;
            As[nxt][aK + 2][aRow + 64] = a1.z; As[nxt][aK + 3][aRow + 64] = a1.w;
            *reinterpret_cast<float4*>(&Bs[nxt][bK][bC]) = b0;
            __syncthreads();
            cur = nxt;
        }
    }
#pragma unroll
    for (int i = 0; i < 8; i++) {
        int r = row0 + ty * 8 + i;
        if (r < GN) {
            float4 v = make_float4(acc[i][0], acc[i][1], acc[i][2], acc[i][3]);
            *reinterpret_cast<float4*>(C + (size_t)r * 256 + coloff + tx * 4) = v;
        }
    }
}

// ---------------- layer1 fused: score + online softmax + aggregate + bias + relu ----------------
// One warp per dst node, 2-edge unrolled for MLP.
__device__ __forceinline__ float score8(const float4& xl0, const float4& xl1,
                                        const float4& xr0, const float4& xr1,
                                        const float4& at0, const float4& at1) {
    float t = lrelu(xl0.x + xr0.x) * at0.x + lrelu(xl0.y + xr0.y) * at0.y
            + lrelu(xl0.z + xr0.z) * at0.z + lrelu(xl0.w + xr0.w) * at0.w
            + lrelu(xl1.x + xr1.x) * at1.x + lrelu(xl1.y + xr1.y) * at1.y
            + lrelu(xl1.z + xr1.z) * at1.z + lrelu(xl1.w + xr1.w) * at1.w;
    return t;
}

__global__ void layer1_fused_kernel(const float* __restrict__ att1,
                                    const float* __restrict__ b1) {
    int gt = blockIdx.x * blockDim.x + threadIdx.x;
    int node = gt >> 5;
    int lane = threadIdx.x & 31;
    if (node >= GN) return;

    const float4* xr4 = reinterpret_cast<const float4*>(g_xr1) + (size_t)node * 64;
    float4 xr0 = xr4[lane * 2];
    float4 xr1 = xr4[lane * 2 + 1];
    float4 at0 = reinterpret_cast<const float4*>(att1)[lane * 2];
    float4 at1 = reinterpret_cast<const float4*>(att1)[lane * 2 + 1];

    float4 acc0 = make_float4(0.f, 0.f, 0.f, 0.f);
    float4 acc1 = make_float4(0.f, 0.f, 0.f, 0.f);
    float m = -CUDART_INF_F, d = 0.0f;

    int beg = g_rowptr[node], end = g_rowptr[node + 1];
    int j = beg;
    for (; j + 2 <= end; j += 2) {
        int s0 = g_csr_src[j];
        int s1 = g_csr_src[j + 1];
        const float4* p0 = reinterpret_cast<const float4*>(g_xl1) + (size_t)s0 * 64 + lane * 2;
        const float4* p1 = reinterpret_cast<const float4*>(g_xl1) + (size_t)s1 * 64 + lane * 2;
        float4 a0 = __ldg(p0);
        float4 a1 = __ldg(p0 + 1);
        float4 c0 = __ldg(p1);
        float4 c1 = __ldg(p1 + 1);

        float t0 = score8(a0, a1, xr0, xr1, at0, at1);
        float t1 = score8(c0, c1, xr0, xr1, at0, at1);
        t0 += __shfl_xor_sync(0xffffffffu, t0, 4);
        t1 += __shfl_xor_sync(0xffffffffu, t1, 4);
        t0 += __shfl_xor_sync(0xffffffffu, t0, 2);
        t1 += __shfl_xor_sync(0xffffffffu, t1, 2);
        t0 += __shfl_xor_sync(0xffffffffu, t0, 1);
        t1 += __shfl_xor_sync(0xffffffffu, t1, 1);

        {
            float mn = fmaxf(m, t0);
            float f = __expf(m - mn);
            float e = __expf(t0 - mn);
            d = d * f + e;
            acc0.x = acc0.x * f + e * a0.x; acc0.y = acc0.y * f + e * a0.y;
            acc0.z = acc0.z * f + e * a0.z; acc0.w = acc0.w * f + e * a0.w;
            acc1.x = acc1.x * f + e * a1.x; acc1.y = acc1.y * f + e * a1.y;
            acc1.z = acc1.z * f + e * a1.z; acc1.w = acc1.w * f + e * a1.w;
            m = mn;
        }
        {
            float mn = fmaxf(m, t1);
            float f = __expf(m - mn);
            float e = __expf(t1 - mn);
            d = d * f + e;
            acc0.x = acc0.x * f + e * c0.x; acc0.y = acc0.y * f + e * c0.y;
            acc0.z = acc0.z * f + e * c0.z; acc0.w = acc0.w * f + e * c0.w;
            acc1.x = acc1.x * f + e * c1.x; acc1.y = acc1.y * f + e * c1.y;
            acc1.z = acc1.z * f + e * c1.z; acc1.w = acc1.w * f + e * c1.w;
            m = mn;
        }
    }
    if (j < end) {
        int s0 = g_csr_src[j];
        const float4* p0 = reinterpret_cast<const float4*>(g_xl1) + (size_t)s0 * 64 + lane * 2;
        float4 a0 = __ldg(p0);
        float4 a1 = __ldg(p0 + 1);
        float t0 = score8(a0, a1, xr0, xr1, at0, at1);
        t0 += __shfl_xor_sync(0xffffffffu, t0, 4);
        t0 += __shfl_xor_sync(0xffffffffu, t0, 2);
        t0 += __shfl_xor_sync(0xffffffffu, t0, 1);
        float mn = fmaxf(m, t0);
        float f = __expf(m - mn);
        float e = __expf(t0 - mn);
        d = d * f + e;
        acc0.x = acc0.x * f + e * a0.x; acc0.y = acc0.y * f + e * a0.y;
        acc0.z = acc0.z * f + e * a0.z; acc0.w = acc0.w * f + e * a0.w;
        acc1.x = acc1.x * f + e * a1.x; acc1.y = acc1.y * f + e * a1.y;
        acc1.z = acc1.z * f + e * a1.z; acc1.w = acc1.w * f + e * a1.w;
        m = mn;
    }

    float inv = 1.0f / d;
    float4 bb0 = reinterpret_cast<const float4*>(b1)[lane * 2];
    float4 bb1 = reinterpret_cast<const float4*>(b1)[lane * 2 + 1];
    float4 o0, o1;
    o0.x = fmaxf(acc0.x * inv + bb0.x, 0.f); o0.y = fmaxf(acc0.y * inv + bb0.y, 0.f);
    o0.z = fmaxf(acc0.z * inv + bb0.z, 0.f); o0.w = fmaxf(acc0.w * inv + bb0.w, 0.f);
    o1.x = fmaxf(acc1.x * inv + bb1.x, 0.f); o1.y = fmaxf(acc1.y * inv + bb1.y, 0.f);
    o1.z = fmaxf(acc1.z * inv + bb1.z, 0.f); o1.w = fmaxf(acc1.w * inv + bb1.w, 0.f);
    float4* out4 = reinterpret_cast<float4*>(g_h) + (size_t)node * 64;
    out4[lane * 2] = o0;
    out4[lane * 2 + 1] = o1;
}

// ---------------- GEMM2: [N,256] x [256,10] twice ----------------
__global__ void gemm2_kernel(const float* __restrict__ Wl2, const float* __restrict__ Wr2) {
    __shared__ float sW[256 * 20];
    int tid = threadIdx.y * 32 + threadIdx.x;
    for (int i = tid; i < 256 * 10; i += 256) {
        int k = i / 10, j = i % 10;
        sW[k * 20 + j] = Wl2[i];
        sW[k * 20 + 10 + j] = Wr2[i];
    }
    __syncthreads();
    int node = blockIdx.x * 8 + threadIdx.y;
    if (node >= GN) return;
    int j = threadIdx.x;
    if (j >= 20) return;
    const float4* hrow4 = reinterpret_cast<const float4*>(g_h + (size_t)node * 256);
    float acc = 0.0f;
#pragma unroll 4
    for (int k4 = 0; k4 < 64; k4++) {
        float4 h = __ldg(&hrow4[k4]);   // broadcast across the 20 lanes
        int k = k4 * 4;
        acc += h.x * sW[(k + 0) * 20 + j];
        acc += h.y * sW[(k + 1) * 20 + j];
        acc += h.z * sW[(k + 2) * 20 + j];
        acc += h.w * sW[(k + 3) * 20 + j];
    }
    if (j < 10) g_hl2[node * 10 + j] = acc;
    else        g_hr2[node * 10 + j - 10] = acc;
}

// ---------------- layer2 fused ----------------
__global__ void layer2_fused_kernel(const float* __restrict__ att2,
                                    const float* __restrict__ b2,
                                    float* __restrict__ out) {
    int gt = blockIdx.x * blockDim.x + threadIdx.x;
    int node = gt >> 5;
    int lane = threadIdx.x & 31;
    if (node >= GN) return;

    float hr = (lane < 10) ? g_hr2[node * 10 + lane] : 0.0f;
    float at = (lane < 10) ? att2[lane] : 0.0f;
    float m = -CUDART_INF_F, d = 0.0f, acc = 0.0f;

    int beg = g_rowptr[node], end = g_rowptr[node + 1];
    for (int j = beg; j < end; j++) {
        int src = g_csr_src[j];
        float hl = (lane < 10) ? __ldg(&g_hl2[src * 10 + lane]) : 0.0f;
        float v = lrelu(hl + hr) * at;
        v += __shfl_xor_sync(0xffffffffu, v, 16);
        v += __shfl_xor_sync(0xffffffffu, v, 8);
        v += __shfl_xor_sync(0xffffffffu, v, 4);
        v += __shfl_xor_sync(0xffffffffu, v, 2);
        v += __shfl_xor_sync(0xffffffffu, v, 1);
        float s = v;
        float mn = fmaxf(m, s);
        float f = __expf(m - mn);
        float e = __expf(s - mn);
        d = d * f + e;
        acc = acc * f + e * hl;
        m = mn;
    }
    if (lane < 10)
        out[node * 10 + lane] = acc / d + b2[lane];
}

// ---------------- launch ----------------
extern "C" void kernel_launch(void* const* d_in, const int* in_sizes, int n_in,
                              void* d_out, int out_size) {
    const float* x    = (const float*)d_in[0];
    const int*   ei   = (const int*)d_in[1];
    const float* Wl1  = (const float*)d_in[2];
    const float* Wr1  = (const float*)d_in[3];
    const float* att1 = (const float*)d_in[4];
    const float* b1   = (const float*)d_in[5];
    const float* Wl2  = (const float*)d_in[6];
    const float* Wr2  = (const float*)d_in[7];
    const float* att2 = (const float*)d_in[8];
    const float* b2   = (const float*)d_in[9];
    float* out = (float*)d_out;

    zero_cnt_kernel<<<(GN + 255) / 256, 256>>>();
    hist_kernel<<<(GET + 255) / 256, 256>>>(ei);
    scan1_kernel<<<NSCAN_BLK, 1024>>>();
    scan2_kernel<<<1, 64>>>();
    scan3_kernel<<<NSCAN_BLK, 1024>>>();
    scatter_kernel<<<(GET + 255) / 256, 256>>>(ei);

    dim3 g1((GN + BM - 1) / BM, 8);
    gemm1_kernel<<<g1, 256>>>(x, Wl1, Wr1);

    layer1_fused_kernel<<<(GN * 32 + 255) / 256, 256>>>(att1, b1);

    gemm2_kernel<<<(GN + 7) / 8, dim3(32, 8)>>>(Wl2, Wr2);

    layer2_fused_kernel<<<(GN * 32 + 255) / 256, 256>>>(att2, b2, out);
}

// round 5
// speedup vs baseline: 2.5809x; 1.4229x over previous
#include <cuda_runtime.h>
#include <cuda_bf16.h>
#include <math_constants.h>
#include <cstdint>

#define GN 50000
#define GE 800000
#define GET (GE + GN)   // edges incl. self loops
#define NSCAN_BLK 49    // ceil(GN/1024)

// ---------------- scratch (device globals; no allocs allowed) ----------------
__device__ __align__(16) float g_xl1[GN * 256];     // x @ W_l1
__device__ __align__(16) float g_xr1[GN * 256];     // x @ W_r1
__device__ __align__(16) float g_hl2[GN * 10];
__device__ __align__(16) float g_hr2[GN * 10];
// K-concat 3-split operands: A' = [hi | hi | lo] (K=768), B' = [hi | lo | hi]
__device__ __align__(16) __nv_bfloat16 g_xs[(size_t)GN * 768];
__device__ __align__(16) __nv_bfloat16 g_ws[512 * 768];   // rows 0-255: Wl cols, 256-511: Wr cols
__device__ int g_cnt[GN];
__device__ int g_rowptr[GN + 1];
__device__ int g_cursor[GN];
__device__ int g_csr_src[GET];
__device__ int g_bsum[NSCAN_BLK];
__device__ int g_boff[NSCAN_BLK];

__device__ __forceinline__ float lrelu(float v) { return v > 0.0f ? v : 0.2f * v; }

__device__ __forceinline__ uint32_t smem_u32(const void* p) {
    uint32_t a;
    asm("{ .reg .u64 t; cvta.to.shared.u64 t, %1; cvt.u32.u64 %0, t; }" : "=r"(a) : "l"(p));
    return a;
}

#define CPA16(dst, src) \
    asm volatile("cp.async.cg.shared.global [%0], [%1], 16;" :: "r"(dst), "l"(src))
#define CPA_COMMIT() asm volatile("cp.async.commit_group;")

__device__ __forceinline__ uint32_t lds_u32(uint32_t addr) {
    uint32_t v;
    asm volatile("ld.shared.b32 %0, [%1];" : "=r"(v) : "r"(addr));
    return v;
}

__device__ __forceinline__ void mma16816(float* c, const uint32_t* a, const uint32_t* b) {
    asm volatile(
        "mma.sync.aligned.m16n8k16.row.col.f32.bf16.bf16.f32 "
        "{%0,%1,%2,%3}, {%4,%5,%6,%7}, {%8,%9}, {%0,%1,%2,%3};"
        : "+f"(c[0]), "+f"(c[1]), "+f"(c[2]), "+f"(c[3])
        : "r"(a[0]), "r"(a[1]), "r"(a[2]), "r"(a[3]), "r"(b[0]), "r"(b[1]));
}

__device__ __forceinline__ uint32_t sw128(uint32_t off) {
    return off ^ ((off >> 3) & 0x70);
}

// ---------------- init: zero histogram ----------------
__global__ void zero_cnt_kernel() {
    int i = blockIdx.x * blockDim.x + threadIdx.x;
    if (i < GN) g_cnt[i] = 0;
}

// ---------------- CSR build ----------------
__global__ void hist_kernel(const int* __restrict__ ei) {
    int e = blockIdx.x * blockDim.x + threadIdx.x;
    if (e >= GET) return;
    int dst = (e < GE) ? ei[GE + e] : (e - GE);
    atomicAdd(&g_cnt[dst], 1);
}

__global__ void scan1_kernel() {
    __shared__ int warp_tot[32];
    int tid = threadIdx.x;
    int i = blockIdx.x * 1024 + tid;
    int lane = tid & 31, wid = tid >> 5;
    int v = (i < GN) ? g_cnt[i] : 0;
    int s = v;
#pragma unroll
    for (int off = 1; off < 32; off <<= 1) {
        int t = __shfl_up_sync(0xffffffffu, s, off);
        if (lane >= off) s += t;
    }
    if (lane == 31) warp_tot[wid] = s;
    __syncthreads();
    if (wid == 0) {
        int w = warp_tot[lane];
        int ws = w;
#pragma unroll
        for (int off = 1; off < 32; off <<= 1) {
            int t = __shfl_up_sync(0xffffffffu, ws, off);
            if (lane >= off) ws += t;
        }
        warp_tot[lane] = ws - w;
        if (lane == 31) g_bsum[blockIdx.x] = ws;
    }
    __syncthreads();
    int excl = s - v + warp_tot[wid];
    if (i < GN) g_rowptr[i] = excl;
}

__global__ void scan2_kernel() {
    int tid = threadIdx.x;
    __shared__ int sh[64];
    int v = (tid < NSCAN_BLK) ? g_bsum[tid] : 0;
    sh[tid] = v;
    __syncthreads();
    if (tid == 0) {
        int run = 0;
        for (int b = 0; b < NSCAN_BLK; b++) { g_boff[b] = run; run += sh[b]; }
        g_rowptr[GN] = GET;
    }
}

__global__ void scan3_kernel() {
    int i = blockIdx.x * 1024 + threadIdx.x;
    if (i >= GN) return;
    int r = g_rowptr[i] + g_boff[blockIdx.x];
    g_rowptr[i] = r;
    g_cursor[i] = r;
}

__global__ void scatter_kernel(const int* __restrict__ ei) {
    int e = blockIdx.x * blockDim.x + threadIdx.x;
    if (e >= GET) return;
    int src, dst;
    if (e < GE) { src = ei[e]; dst = ei[GE + e]; }
    else        { src = dst = e - GE; }
    int pos = atomicAdd(&g_cursor[dst], 1);
    g_csr_src[pos] = src;
}

// ---------------- bf16 K-concat split conversions ----------------
__global__ void convert_x_kernel(const float* __restrict__ x) {
    int i = blockIdx.x * blockDim.x + threadIdx.x;   // over GN*64 float4s
    if (i >= GN * 64) return;
    int row = i >> 6, k4 = (i & 63) * 4;
    float4 v = reinterpret_cast<const float4*>(x)[i];
    __nv_bfloat16 h0 = __float2bfloat16(v.x), h1 = __float2bfloat16(v.y);
    __nv_bfloat16 h2 = __float2bfloat16(v.z), h3 = __float2bfloat16(v.w);
    __nv_bfloat16 l0 = __float2bfloat16(v.x - __bfloat162float(h0));
    __nv_bfloat16 l1 = __float2bfloat16(v.y - __bfloat162float(h1));
    __nv_bfloat16 l2 = __float2bfloat16(v.z - __bfloat162float(h2));
    __nv_bfloat16 l3 = __float2bfloat16(v.w - __bfloat162float(h3));
    __nv_bfloat162 hA(h0, h1), hB(h2, h3), lA(l0, l1), lB(l2, l3);
    size_t base = (size_t)row * 768 + k4;
    __nv_bfloat162* p0 = reinterpret_cast<__nv_bfloat162*>(&g_xs[base]);
    __nv_bfloat162* p1 = reinterpret_cast<__nv_bfloat162*>(&g_xs[base + 256]);
    __nv_bfloat162* p2 = reinterpret_cast<__nv_bfloat162*>(&g_xs[base + 512]);
    p0[0] = hA; p0[1] = hB;
    p1[0] = hA; p1[1] = hB;
    p2[0] = lA; p2[1] = lB;
}

__global__ void convert_w_kernel(const float* __restrict__ Wl1, const float* __restrict__ Wr1) {
    int i = blockIdx.x * blockDim.x + threadIdx.x;   // 512*256
    if (i >= 512 * 256) return;
    int n = i >> 8, k = i & 255;
    float w = (n < 256) ? Wl1[k * 256 + n] : Wr1[k * 256 + (n - 256)];
    __nv_bfloat16 h = __float2bfloat16(w);
    __nv_bfloat16 l = __float2bfloat16(w - __bfloat162float(h));
    size_t base = (size_t)n * 768;
    g_ws[base + k] = h;
    g_ws[base + 256 + k] = l;
    g_ws[base + 512 + k] = h;
}

// ---------------- GEMM1 via mma.sync bf16 (M=50000, N=512, K=768) ----------------
// CTA tile 128x64, BK=64, 8 warps (4M x 2N), warp tile 32x32, cp.async double buffer.
#define GBM 128
#define GBN 64
#define GBK 64
#define A_STAGE (GBM * GBK * 2)           // 16384
#define B_STAGE (GBN * GBK * 2)           // 8192
#define STAGE_BYTES (A_STAGE + B_STAGE)   // 24576
#define KITERS 12                          // 768/64

__global__ void __launch_bounds__(256, 2) gemm1_mma_kernel() {
    __shared__ __align__(128) char smem[2 * STAGE_BYTES];
    uint32_t sb = smem_u32(smem);
    int tid = threadIdx.x;
    int wid = tid >> 5, lane = tid & 31;
    int rb = blockIdx.x, nb = blockIdx.y;
    int row0 = rb * GBM;
    int g = lane >> 2, t2 = (lane & 3) * 2;
    int warpM = wid & 3, warpN = wid >> 2;

    const char* Ab = (const char*)g_xs;
    const char* Bb = (const char*)g_ws;

    float c[2][4][4];
#pragma unroll
    for (int mt = 0; mt < 2; mt++)
#pragma unroll
        for (int nt = 0; nt < 4; nt++)
#pragma unroll
            for (int q = 0; q < 4; q++) c[mt][nt][q] = 0.0f;

    auto issue = [&](int kt, int buf) {
        uint32_t sA = sb + buf * STAGE_BYTES;
        uint32_t sB = sA + A_STAGE;
        int kc = kt * GBK;
#pragma unroll
        for (int q = 0; q < 4; q++) {
            int id = tid + q * 256;
            int m = id >> 3, ch = id & 7;
            int grow = row0 + m; if (grow >= GN) grow = 0;
            const char* src = Ab + (size_t)grow * 1536 + kc * 2 + ch * 16;
            CPA16(sA + sw128(m * 128 + ch * 16), src);
        }
#pragma unroll
        for (int q = 0; q < 2; q++) {
            int id = tid + q * 256;
            int n = id >> 3, ch = id & 7;
            const char* src = Bb + (size_t)(nb * 64 + n) * 1536 + kc * 2 + ch * 16;
            CPA16(sB + sw128(n * 128 + ch * 16), src);
        }
        CPA_COMMIT();
    };

    issue(0, 0);
    for (int t = 0; t < KITERS; t++) {
        if (t + 1 < KITERS) {
            issue(t + 1, (t + 1) & 1);
            asm volatile("cp.async.wait_group 1;");
        } else {
            asm volatile("cp.async.wait_group 0;");
        }
        __syncthreads();
        uint32_t sA = sb + (t & 1) * STAGE_BYTES;
        uint32_t sB = sA + A_STAGE;
#pragma unroll
        for (int ks = 0; ks < 4; ks++) {
            int kb = ks * 16;
            uint32_t a[2][4], b[4][2];
#pragma unroll
            for (int mt = 0; mt < 2; mt++) {
                int m0 = warpM * 32 + mt * 16 + g;
                a[mt][0] = lds_u32(sA + sw128(m0 * 128 + (kb + t2) * 2));
                a[mt][1] = lds_u32(sA + sw128((m0 + 8) * 128 + (kb + t2) * 2));
                a[mt][2] = lds_u32(sA + sw128(m0 * 128 + (kb + t2 + 8) * 2));
                a[mt][3] = lds_u32(sA + sw128((m0 + 8) * 128 + (kb + t2 + 8) * 2));
            }
#pragma unroll
            for (int nt = 0; nt < 4; nt++) {
                int n0 = warpN * 32 + nt * 8 + g;
                b[nt][0] = lds_u32(sB + sw128(n0 * 128 + (kb + t2) * 2));
                b[nt][1] = lds_u32(sB + sw128(n0 * 128 + (kb + t2 + 8) * 2));
            }
#pragma unroll
            for (int mt = 0; mt < 2; mt++)
#pragma unroll
                for (int nt = 0; nt < 4; nt++)
                    mma16816(c[mt][nt], a[mt], b[nt]);
        }
        __syncthreads();
    }

    float* C = (nb < 4) ? g_xl1 : g_xr1;
    int colBase = (nb & 3) * 64 + warpN * 32;
#pragma unroll
    for (int mt = 0; mt < 2; mt++) {
        int r0 = row0 + warpM * 32 + mt * 16 + g;
#pragma unroll
        for (int nt = 0; nt < 4; nt++) {
            int cc = colBase + nt * 8 + t2;
            if (r0 < GN)
                *reinterpret_cast<float2*>(C + (size_t)r0 * 256 + cc) =
                    make_float2(c[mt][nt][0], c[mt][nt][1]);
            if (r0 + 8 < GN)
                *reinterpret_cast<float2*>(C + (size_t)(r0 + 8) * 256 + cc) =
                    make_float2(c[mt][nt][2], c[mt][nt][3]);
        }
    }
}

// ---------------- layer1 fused: softmax-aggregate + bias/relu + (h @ W2) ----------------
__device__ __forceinline__ float score8(const float4& xl0, const float4& xl1,
                                        const float4& xr0, const float4& xr1,
                                        const float4& at0, const float4& at1) {
    float t = lrelu(xl0.x + xr0.x) * at0.x + lrelu(xl0.y + xr0.y) * at0.y
            + lrelu(xl0.z + xr0.z) * at0.z + lrelu(xl0.w + xr0.w) * at0.w
            + lrelu(xl1.x + xr1.x) * at1.x + lrelu(xl1.y + xr1.y) * at1.y
            + lrelu(xl1.z + xr1.z) * at1.z + lrelu(xl1.w + xr1.w) * at1.w;
    return t;
}

__global__ void layer1_fused_kernel(const float* __restrict__ att1,
                                    const float* __restrict__ b1,
                                    const float* __restrict__ Wl2,
                                    const float* __restrict__ Wr2) {
    // sW[q][lane][jj] (jj padded to 21): W2cat[lane*8+q][jj], conflict-free reads
    __shared__ float sW[8 * 32 * 21];
    int tid = threadIdx.x;
    for (int i = tid; i < 8 * 32 * 20; i += 256) {
        int jj = i % 20;
        int cidx = i / 20;            // 0..255 channel
        int q = cidx & 7, ls = cidx >> 3;
        float w = (jj < 10) ? Wl2[cidx * 10 + jj] : Wr2[cidx * 10 + (jj - 10)];
        sW[q * (32 * 21) + ls * 21 + jj] = w;
    }
    __syncthreads();

    int gt = blockIdx.x * blockDim.x + tid;
    int node = gt >> 5;
    int lane = tid & 31;
    if (node >= GN) return;

    const float4* xr4 = reinterpret_cast<const float4*>(g_xr1) + (size_t)node * 64;
    float4 xr0 = xr4[lane * 2];
    float4 xr1 = xr4[lane * 2 + 1];
    float4 at0 = reinterpret_cast<const float4*>(att1)[lane * 2];
    float4 at1 = reinterpret_cast<const float4*>(att1)[lane * 2 + 1];

    float4 acc0 = make_float4(0.f, 0.f, 0.f, 0.f);
    float4 acc1 = make_float4(0.f, 0.f, 0.f, 0.f);
    float m = -CUDART_INF_F, d = 0.0f;

    int beg = g_rowptr[node], end = g_rowptr[node + 1];
    int j = beg;
    for (; j + 2 <= end; j += 2) {
        int s0 = g_csr_src[j];
        int s1 = g_csr_src[j + 1];
        const float4* p0 = reinterpret_cast<const float4*>(g_xl1) + (size_t)s0 * 64 + lane * 2;
        const float4* p1 = reinterpret_cast<const float4*>(g_xl1) + (size_t)s1 * 64 + lane * 2;
        float4 a0 = __ldg(p0);
        float4 a1 = __ldg(p0 + 1);
        float4 c0 = __ldg(p1);
        float4 c1 = __ldg(p1 + 1);

        float t0 = score8(a0, a1, xr0, xr1, at0, at1);
        float t1 = score8(c0, c1, xr0, xr1, at0, at1);
        t0 += __shfl_xor_sync(0xffffffffu, t0, 4);
        t1 += __shfl_xor_sync(0xffffffffu, t1, 4);
        t0 += __shfl_xor_sync(0xffffffffu, t0, 2);
        t1 += __shfl_xor_sync(0xffffffffu, t1, 2);
        t0 += __shfl_xor_sync(0xffffffffu, t0, 1);
        t1 += __shfl_xor_sync(0xffffffffu, t1, 1);

        {
            float mn = fmaxf(m, t0);
            float f = __expf(m - mn);
            float e = __expf(t0 - mn);
            d = d * f + e;
            acc0.x = acc0.x * f + e * a0.x; acc0.y = acc0.y * f + e * a0.y;
            acc0.z = acc0.z * f + e * a0.z; acc0.w = acc0.w * f + e * a0.w;
            acc1.x = acc1.x * f + e * a1.x; acc1.y = acc1.y * f + e * a1.y;
            acc1.z = acc1.z * f + e * a1.z; acc1.w = acc1.w * f + e * a1.w;
            m = mn;
        }
        {
            float mn = fmaxf(m, t1);
            float f = __expf(m - mn);
            float e = __expf(t1 - mn);
            d = d * f + e;
            acc0.x = acc0.x * f + e * c0.x; acc0.y = acc0.y * f + e * c0.y;
            acc0.z = acc0.z * f + e * c0.z; acc0.w = acc0.w * f + e * c0.w;
            acc1.x = acc1.x * f + e * c1.x; acc1.y = acc1.y * f + e * c1.y;
            acc1.z = acc1.z * f + e * c1.z; acc1.w = acc1.w * f + e * c1.w;
            m = mn;
        }
    }
    if (j < end) {
        int s0 = g_csr_src[j];
        const float4* p0 = reinterpret_cast<const float4*>(g_xl1) + (size_t)s0 * 64 + lane * 2;
        float4 a0 = __ldg(p0);
        float4 a1 = __ldg(p0 + 1);
        float t0 = score8(a0, a1, xr0, xr1, at0, at1);
        t0 += __shfl_xor_sync(0xffffffffu, t0, 4);
        t0 += __shfl_xor_sync(0xffffffffu, t0, 2);
        t0 += __shfl_xor_sync(0xffffffffu, t0, 1);
        float mn = fmaxf(m, t0);
        float f = __expf(m - mn);
        float e = __expf(t0 - mn);
        d = d * f + e;
        acc0.x = acc0.x * f + e * a0.x; acc0.y = acc0.y * f + e * a0.y;
        acc0.z = acc0.z * f + e * a0.z; acc0.w = acc0.w * f + e * a0.w;
        acc1.x = acc1.x * f + e * a1.x; acc1.y = acc1.y * f + e * a1.y;
        acc1.z = acc1.z * f + e * a1.z; acc1.w = acc1.w * f + e * a1.w;
        m = mn;
    }

    float inv = 1.0f / d;
    float4 bb0 = reinterpret_cast<const float4*>(b1)[lane * 2];
    float4 bb1 = reinterpret_cast<const float4*>(b1)[lane * 2 + 1];
    float hv[8];
    hv[0] = fmaxf(acc0.x * inv + bb0.x, 0.f); hv[1] = fmaxf(acc0.y * inv + bb0.y, 0.f);
    hv[2] = fmaxf(acc0.z * inv + bb0.z, 0.f); hv[3] = fmaxf(acc0.w * inv + bb0.w, 0.f);
    hv[4] = fmaxf(acc1.x * inv + bb1.x, 0.f); hv[5] = fmaxf(acc1.y * inv + bb1.y, 0.f);
    hv[6] = fmaxf(acc1.z * inv + bb1.z, 0.f); hv[7] = fmaxf(acc1.w * inv + bb1.w, 0.f);

    // fused h @ [Wl2 | Wr2]: 20 outputs per node
    const float* sWl = &sW[lane * 21];
    float myval = 0.0f;
#pragma unroll
    for (int jj = 0; jj < 20; jj++) {
        float s = 0.0f;
#pragma unroll
        for (int q = 0; q < 8; q++)
            s += hv[q] * sWl[q * (32 * 21) + jj];
        s += __shfl_xor_sync(0xffffffffu, s, 16);
        s += __shfl_xor_sync(0xffffffffu, s, 8);
        s += __shfl_xor_sync(0xffffffffu, s, 4);
        s += __shfl_xor_sync(0xffffffffu, s, 2);
        s += __shfl_xor_sync(0xffffffffu, s, 1);
        if (lane == jj) myval = s;
    }
    if (lane < 10)       g_hl2[node * 10 + lane] = myval;
    else if (lane < 20)  g_hr2[node * 10 + lane - 10] = myval;
}

// ---------------- layer2 fused ----------------
__global__ void layer2_fused_kernel(const float* __restrict__ att2,
                                    const float* __restrict__ b2,
                                    float* __restrict__ out) {
    int gt = blockIdx.x * blockDim.x + threadIdx.x;
    int node = gt >> 5;
    int lane = threadIdx.x & 31;
    if (node >= GN) return;

    float hr = (lane < 10) ? g_hr2[node * 10 + lane] : 0.0f;
    float at = (lane < 10) ? att2[lane] : 0.0f;
    float m = -CUDART_INF_F, d = 0.0f, acc = 0.0f;

    int beg = g_rowptr[node], end = g_rowptr[node + 1];
    for (int j = beg; j < end; j++) {
        int src = g_csr_src[j];
        float hl = (lane < 10) ? __ldg(&g_hl2[src * 10 + lane]) : 0.0f;
        float v = lrelu(hl + hr) * at;
        v += __shfl_xor_sync(0xffffffffu, v, 16);
        v += __shfl_xor_sync(0xffffffffu, v, 8);
        v += __shfl_xor_sync(0xffffffffu, v, 4);
        v += __shfl_xor_sync(0xffffffffu, v, 2);
        v += __shfl_xor_sync(0xffffffffu, v, 1);
        float s = v;
        float mn = fmaxf(m, s);
        float f = __expf(m - mn);
        float e = __expf(s - mn);
        d = d * f + e;
        acc = acc * f + e * hl;
        m = mn;
    }
    if (lane < 10)
        out[node * 10 + lane] = acc / d + b2[lane];
}

// ---------------- launch ----------------
extern "C" void kernel_launch(void* const* d_in, const int* in_sizes, int n_in,
                              void* d_out, int out_size) {
    const float* x    = (const float*)d_in[0];
    const int*   ei   = (const int*)d_in[1];
    const float* Wl1  = (const float*)d_in[2];
    const float* Wr1  = (const float*)d_in[3];
    const float* att1 = (const float*)d_in[4];
    const float* b1   = (const float*)d_in[5];
    const float* Wl2  = (const float*)d_in[6];
    const float* Wr2  = (const float*)d_in[7];
    const float* att2 = (const float*)d_in[8];
    const float* b2   = (const float*)d_in[9];
    float* out = (float*)d_out;

    zero_cnt_kernel<<<(GN + 255) / 256, 256>>>();
    hist_kernel<<<(GET + 255) / 256, 256>>>(ei);
    convert_x_kernel<<<(GN * 64 + 255) / 256, 256>>>(x);
    convert_w_kernel<<<(512 * 256 + 255) / 256, 256>>>(Wl1, Wr1);
    scan1_kernel<<<NSCAN_BLK, 1024>>>();
    scan2_kernel<<<1, 64>>>();
    scan3_kernel<<<NSCAN_BLK, 1024>>>();
    scatter_kernel<<<(GET + 255) / 256, 256>>>(ei);

    dim3 g1((GN + GBM - 1) / GBM, 8);
    gemm1_mma_kernel<<<g1, 256>>>();

    layer1_fused_kernel<<<(GN * 32 + 255) / 256, 256>>>(att1, b1, Wl2, Wr2);

    layer2_fused_kernel<<<(GN * 32 + 255) / 256, 256>>>(att2, b2, out);
}